// round 14
// baseline (speedup 1.0000x reference)
#include <cuda_runtime.h>
#include <cstdint>
#include <cstddef>
#include <math.h>

#define B_TOT 131072
#define D_IN  128
#define HID   256
#define VTOT  6
#define TSTEPS 6

typedef unsigned long long ull;

extern "C" __device__ float __nv_logf(float);
extern "C" __device__ float __nv_expf(float);

// ---------------- persistent device scratch ---------------------------------
__device__ __align__(16) float g_h [(size_t)B_TOT * HID];
__device__ __align__(16) float g_z [(size_t)B_TOT * HID];
__device__ __align__(16) float g_rh[(size_t)B_TOT * HID];
__device__ unsigned char g_state[B_TOT];
__device__ __align__(16) float g_E[3][8][HID];
__device__ uint32_t g_keyw[12];
__device__ int g_perm[2][B_TOT];
__device__ int g_cnt[TSTEPS + 2];

// ---------------- threefry2x32 (exact JAX schedule) -------------------------
__device__ __forceinline__ void threefry2x32(uint32_t k0, uint32_t k1,
                                             uint32_t c0, uint32_t c1,
                                             uint32_t& o0, uint32_t& o1) {
  uint32_t ks2 = k0 ^ k1 ^ 0x1BD11BDAu;
  uint32_t x0 = c0 + k0, x1 = c1 + k1;
#define TF_R(r) { x0 += x1; x1 = (x1 << (r)) | (x1 >> (32 - (r))); x1 ^= x0; }
  TF_R(13) TF_R(15) TF_R(26) TF_R(6)
  x0 += k1;  x1 += ks2 + 1u;
  TF_R(17) TF_R(29) TF_R(16) TF_R(24)
  x0 += ks2; x1 += k0 + 2u;
  TF_R(13) TF_R(15) TF_R(26) TF_R(6)
  x0 += k0;  x1 += k1 + 3u;
  TF_R(17) TF_R(29) TF_R(16) TF_R(24)
  x0 += k1;  x1 += ks2 + 4u;
  TF_R(13) TF_R(15) TF_R(26) TF_R(6)
  x0 += ks2; x1 += k0 + 5u;
#undef TF_R
  o0 = x0; o1 = x1;
}

// ---------------- helpers -----------------------------------------------------
__device__ __forceinline__ void fma2(ull& d, ull a, ull b) {
  asm("fma.rn.f32x2 %0, %1, %2, %0;" : "+l"(d) : "l"(a), "l"(b));
}
__device__ __forceinline__ ull pack2(float a) {
  ull r; asm("mov.b64 %0, {%1, %1};" : "=l"(r) : "f"(a)); return r;
}
__device__ __forceinline__ float2 unpack2(ull v) {
  float2 r; asm("mov.b64 {%0, %1}, %2;" : "=f"(r.x), "=f"(r.y) : "l"(v)); return r;
}
__device__ __forceinline__ void cp16(void* dst, const void* src) {
  unsigned d = (unsigned)__cvta_generic_to_shared(dst);
  asm volatile("cp.async.cg.shared.global [%0], [%1], 16;" :: "r"(d), "l"(src));
}
__device__ __forceinline__ float xla_tanh(float x) {
  float ax = fabsf(x);
  if (ax < 0.0004f) return x;
  float xc = fminf(fmaxf(x, -9.0f), 9.0f);
  float x2 = __fmul_rn(xc, xc);
  float num = -2.76076847742355e-16f;
  num = __fadd_rn(__fmul_rn(x2, num), 2.00018790482477e-13f);
  num = __fadd_rn(__fmul_rn(x2, num), -8.60467152213735e-11f);
  num = __fadd_rn(__fmul_rn(x2, num), 5.12229709037114e-08f);
  num = __fadd_rn(__fmul_rn(x2, num), 1.48572235717979e-05f);
  num = __fadd_rn(__fmul_rn(x2, num), 6.37261928875436e-04f);
  num = __fadd_rn(__fmul_rn(x2, num), 4.89352455891786e-03f);
  num = __fmul_rn(xc, num);
  float den = 1.19825839466702e-06f;
  den = __fadd_rn(__fmul_rn(x2, den), 1.18534705686654e-04f);
  den = __fadd_rn(__fmul_rn(x2, den), 2.26843463243900e-03f);
  den = __fadd_rn(__fmul_rn(x2, den), 4.89352518554385e-03f);
  return __fdiv_rn(num, den);
}
__device__ __forceinline__ float sigmoid_(float x) {
  return __fadd_rn(0.5f, __fmul_rn(0.5f, xla_tanh(__fmul_rn(0.5f, x))));
}

// ---------------- init --------------------------------------------------------
__global__ void init_kernel(float* __restrict__ out) {
  const int gid = blockIdx.x * blockDim.x + threadIdx.x;
  if (gid < B_TOT) {
    out[(size_t)B_TOT * 36 + gid] = 0.f;
    out[(size_t)B_TOT * 37 + gid] = 0.f;
    g_state[gid] = 7;
    g_perm[0][gid] = gid;
  }
  if (gid < TSTEPS + 2) g_cnt[gid] = (gid == 0) ? B_TOT : 0;
  if (gid < 6) {
    uint32_t a, b;
    threefry2x32(0u, 42u, 0u, (uint32_t)gid, a, b);
    g_keyw[2 * gid]     = a;
    g_keyw[2 * gid + 1] = b;
  }
}

// ---------------- precompute E tables ----------------------------------------
__global__ void precompute_E(const float* __restrict__ W_embed,
                             const float* __restrict__ b_embed,
                             const float* __restrict__ Wz, const float* __restrict__ bz,
                             const float* __restrict__ Wr, const float* __restrict__ br,
                             const float* __restrict__ Wh, const float* __restrict__ bh,
                             const float* __restrict__ start_embed) {
  int s = blockIdx.x, m = blockIdx.y, j = threadIdx.x;
  const float* W  = (m == 0) ? Wz : (m == 1) ? Wr : Wh;
  const float* bb = (m == 0) ? bz : (m == 1) ? br : bh;
  float acc = bb[j];
  for (int k = 0; k < HID; k++) {
    float e;
    if (s == 7) e = start_embed[k];
    else { e = b_embed[k]; if (s < 6) e += W_embed[s * HID + k]; }
    acc = fmaf(e, W[k * HID + j], acc);
  }
  g_E[m][s][j] = acc;
}

// ---------------- GEMM core (R8 proven config: BM64/BN256/BK16) --------------
// MODE 0: encoder (no perm)           -> g_h = acc + b_enc
// MODE 12: z|r by blockIdx.y, A=g_h   -> g_z = sig(acc+E_z) | g_rh = sig(acc+E_r)*g_h
// MODE 3: cand, A=g_rh                -> g_h = (1-z)*h + z*tanh(acc+E_h)
template <int MODE>
__global__ void __launch_bounds__(256, 2) gemm_k(
    const float* __restrict__ Aext, int lda, int K,
    const float* __restrict__ Bw0, const float* __restrict__ Bw1,
    const float* __restrict__ bias, int t) {
  constexpr int BM = 64, BN = 256, BK = 16, APAD = BM + 4;
  __shared__ __align__(16) float As[2][BK][APAD];
  __shared__ __align__(16) float Bs[2][BK][BN];
  __shared__ int sPerm[BM];

  const int gate = (MODE == 12) ? blockIdx.y : 0;            // 0=z, 1=r
  const int emIdx = (MODE == 12) ? gate : 2;                 // E table row
  const float* Bw = (MODE == 12 && gate == 1) ? Bw1 : Bw0;

  const int rowBase = blockIdx.x * BM;
  int cnt = B_TOT;
  if (MODE != 0) {
    cnt = g_cnt[t];
    if (rowBase >= cnt) return;
    const int* perm = g_perm[t & 1];
    if (threadIdx.x < BM) {
      int j = rowBase + threadIdx.x;
      sPerm[threadIdx.x] = perm[j < cnt ? j : rowBase];
    }
    __syncthreads();
  }

  const float* A = (MODE == 0) ? Aext : (MODE == 3 ? g_rh : g_h);
  const int tid = threadIdx.x;
  const int tc = tid & 31;
  const int tr = tid >> 5;

  const int a_row = tid >> 2;
  const int a_seg = (tid & 3) << 2;
  const int arow_g = (MODE == 0) ? (rowBase + a_row) : sPerm[a_row];
  const float* Ag = A + (size_t)arow_g * lda + a_seg;

  ull acc[8][4];
#pragma unroll
  for (int r = 0; r < 8; r++)
#pragma unroll
    for (int p = 0; p < 4; p++) acc[r][p] = 0ull;

  const int NC = K / BK;

  float4 rA = *reinterpret_cast<const float4*>(Ag);
#pragma unroll
  for (int i = 0; i < 4; i++) {
    int idx = tid + i * 256, kr = idx >> 6, cs = (idx & 63) << 2;
    cp16(&Bs[0][kr][cs], Bw + (size_t)kr * BN + cs);
  }
  asm volatile("cp.async.commit_group;");
  As[0][a_seg + 0][a_row] = rA.x;
  As[0][a_seg + 1][a_row] = rA.y;
  As[0][a_seg + 2][a_row] = rA.z;
  As[0][a_seg + 3][a_row] = rA.w;
  if (NC > 1) rA = *reinterpret_cast<const float4*>(Ag + BK);

  for (int c = 0; c < NC; c++) {
    asm volatile("cp.async.wait_group 0;");
    __syncthreads();
    if (c + 1 < NC) {
      const int nbuf = (c + 1) & 1;
#pragma unroll
      for (int i = 0; i < 4; i++) {
        int idx = tid + i * 256, kr = idx >> 6, cs = (idx & 63) << 2;
        cp16(&Bs[nbuf][kr][cs], Bw + (size_t)((c + 1) * BK + kr) * BN + cs);
      }
      asm volatile("cp.async.commit_group;");
      As[nbuf][a_seg + 0][a_row] = rA.x;
      As[nbuf][a_seg + 1][a_row] = rA.y;
      As[nbuf][a_seg + 2][a_row] = rA.z;
      As[nbuf][a_seg + 3][a_row] = rA.w;
      if (c + 2 < NC) rA = *reinterpret_cast<const float4*>(Ag + (c + 2) * BK);
    }
    const int buf = c & 1;
#pragma unroll
    for (int k = 0; k < BK; k++) {
      ulonglong2 b01 = *reinterpret_cast<const ulonglong2*>(&Bs[buf][k][tc * 4]);
      ulonglong2 b23 = *reinterpret_cast<const ulonglong2*>(&Bs[buf][k][128 + tc * 4]);
      float4 a0 = *reinterpret_cast<const float4*>(&As[buf][k][tr * 8]);
      float4 a1 = *reinterpret_cast<const float4*>(&As[buf][k][tr * 8 + 4]);
      ull ap[8];
      ap[0] = pack2(a0.x); ap[1] = pack2(a0.y); ap[2] = pack2(a0.z); ap[3] = pack2(a0.w);
      ap[4] = pack2(a1.x); ap[5] = pack2(a1.y); ap[6] = pack2(a1.z); ap[7] = pack2(a1.w);
#pragma unroll
      for (int r = 0; r < 8; r++) {
        fma2(acc[r][0], ap[r], b01.x);
        fma2(acc[r][1], ap[r], b01.y);
        fma2(acc[r][2], ap[r], b23.x);
        fma2(acc[r][3], ap[r], b23.y);
      }
    }
  }

  const int c0 = tc * 4;
#pragma unroll
  for (int r = 0; r < 8; r++) {
    const int iRow = rowBase + tr * 8 + r;
    if (MODE != 0 && iRow >= cnt) continue;
    const int rr = (MODE == 0) ? iRow : sPerm[tr * 8 + r];
    float f[8];
    {
      float2 v;
      v = unpack2(acc[r][0]); f[0] = v.x; f[1] = v.y;
      v = unpack2(acc[r][1]); f[2] = v.x; f[3] = v.y;
      v = unpack2(acc[r][2]); f[4] = v.x; f[5] = v.y;
      v = unpack2(acc[r][3]); f[6] = v.x; f[7] = v.y;
    }
    const size_t base0 = (size_t)rr * HID + c0;
    const size_t base1 = base0 + 128;
    if (MODE == 0) {
      float4 b0 = *reinterpret_cast<const float4*>(&bias[c0]);
      float4 b1 = *reinterpret_cast<const float4*>(&bias[128 + c0]);
      *reinterpret_cast<float4*>(&g_h[base0]) =
          make_float4(f[0] + b0.x, f[1] + b0.y, f[2] + b0.z, f[3] + b0.w);
      *reinterpret_cast<float4*>(&g_h[base1]) =
          make_float4(f[4] + b1.x, f[5] + b1.y, f[6] + b1.z, f[7] + b1.w);
    } else {
      const int s = g_state[rr] & 7;
      const float* Em = g_E[emIdx][s];
      float4 e0 = *reinterpret_cast<const float4*>(&Em[c0]);
      float4 e1 = *reinterpret_cast<const float4*>(&Em[128 + c0]);
      float pre[8] = {f[0] + e0.x, f[1] + e0.y, f[2] + e0.z, f[3] + e0.w,
                      f[4] + e1.x, f[5] + e1.y, f[6] + e1.z, f[7] + e1.w};
      if (MODE == 12 && gate == 0) {
        *reinterpret_cast<float4*>(&g_z[base0]) =
            make_float4(sigmoid_(pre[0]), sigmoid_(pre[1]),
                        sigmoid_(pre[2]), sigmoid_(pre[3]));
        *reinterpret_cast<float4*>(&g_z[base1]) =
            make_float4(sigmoid_(pre[4]), sigmoid_(pre[5]),
                        sigmoid_(pre[6]), sigmoid_(pre[7]));
      } else if (MODE == 12) {
        float4 h0 = *reinterpret_cast<const float4*>(&g_h[base0]);
        float4 h1 = *reinterpret_cast<const float4*>(&g_h[base1]);
        *reinterpret_cast<float4*>(&g_rh[base0]) =
            make_float4(sigmoid_(pre[0]) * h0.x, sigmoid_(pre[1]) * h0.y,
                        sigmoid_(pre[2]) * h0.z, sigmoid_(pre[3]) * h0.w);
        *reinterpret_cast<float4*>(&g_rh[base1]) =
            make_float4(sigmoid_(pre[4]) * h1.x, sigmoid_(pre[5]) * h1.y,
                        sigmoid_(pre[6]) * h1.z, sigmoid_(pre[7]) * h1.w);
      } else {  // MODE 3
        float4 z0 = *reinterpret_cast<const float4*>(&g_z[base0]);
        float4 z1 = *reinterpret_cast<const float4*>(&g_z[base1]);
        float4 h0 = *reinterpret_cast<const float4*>(&g_h[base0]);
        float4 h1 = *reinterpret_cast<const float4*>(&g_h[base1]);
        float4 o0, o1;
        o0.x = (1.f - z0.x) * h0.x + z0.x * xla_tanh(pre[0]);
        o0.y = (1.f - z0.y) * h0.y + z0.y * xla_tanh(pre[1]);
        o0.z = (1.f - z0.z) * h0.z + z0.z * xla_tanh(pre[2]);
        o0.w = (1.f - z0.w) * h0.w + z0.w * xla_tanh(pre[3]);
        o1.x = (1.f - z1.x) * h1.x + z1.x * xla_tanh(pre[4]);
        o1.y = (1.f - z1.y) * h1.y + z1.y * xla_tanh(pre[5]);
        o1.z = (1.f - z1.z) * h1.z + z1.z * xla_tanh(pre[6]);
        o1.w = (1.f - z1.w) * h1.w + z1.w * xla_tanh(pre[7]);
        *reinterpret_cast<float4*>(&g_h[base0]) = o0;
        *reinterpret_cast<float4*>(&g_h[base1]) = o1;
      }
    }
  }
}

// ---------------- sampler v2 + compaction (R8, unchanged) ---------------------
__global__ void __launch_bounds__(256) sample_step(
    const float* __restrict__ W_out, const float* __restrict__ b_out,
    float* __restrict__ out, int t) {
  __shared__ float Ws[HID * VTOT];
  __shared__ float bs[8];
  __shared__ int wcnt[8], wpre[8], sbase;
  const int cnt = g_cnt[t];
  const int base_i = blockIdx.x * 64;
  if (base_i >= cnt) return;
  const int* perm = g_perm[t & 1];
  int* permN = g_perm[(t + 1) & 1];
  const int tid = threadIdx.x;
  for (int i = tid; i < HID * VTOT; i += 256) Ws[i] = W_out[i];
  if (tid < VTOT) bs[tid] = b_out[tid];
  __syncthreads();
  const int wid = tid >> 5, lane = tid & 31;
  const int g = lane & 3, rloc = lane >> 2;
  const int i = base_i + wid * 8 + rloc;
  const bool valid = (i < cnt);
  const int row = perm[valid ? i : base_i];
  const float* h = g_h + (size_t)row * HID + g * 64;
  float p[VTOT];
#pragma unroll
  for (int v = 0; v < VTOT; v++) p[v] = 0.f;
#pragma unroll
  for (int q = 0; q < 16; q++) {
    float4 hv = *reinterpret_cast<const float4*>(h + q * 4);
    const float* w = &Ws[(g * 64 + q * 4) * VTOT];
#pragma unroll
    for (int v = 0; v < VTOT; v++) {
      p[v] = fmaf(hv.x, w[v], p[v]);
      p[v] = fmaf(hv.y, w[VTOT + v], p[v]);
      p[v] = fmaf(hv.z, w[2 * VTOT + v], p[v]);
      p[v] = fmaf(hv.w, w[3 * VTOT + v], p[v]);
    }
  }
#pragma unroll
  for (int o = 1; o <= 2; o <<= 1)
#pragma unroll
    for (int v = 0; v < VTOT; v++) p[v] += __shfl_xor_sync(0xffffffffu, p[v], o);
  const uint32_t k0 = g_keyw[2 * t], k1 = g_keyw[2 * t + 1];
  float y_best = __int_as_float(0xff800000);
  int tok_best = 127;
  if (g < 3) {
#pragma unroll
    for (int j = 0; j < 2; j++) {
      const int v = 2 * g + j;
      uint32_t idx = (uint32_t)row * VTOT + v;
      uint32_t o0, o1;
      threefry2x32(k0, k1, 0u, idx, o0, o1);
      uint32_t bits = o0 ^ o1;
      uint32_t fb = (bits >> 9) | 0x3f800000u;
      float fu = __fadd_rn(__uint_as_float(fb), -1.0f);
      float u = fmaxf(1.17549435e-38f, fu);
      float gf = -__nv_logf(-__nv_logf(u));
      float y = (p[v] + bs[v]) + gf;
      if (y > y_best) { y_best = y; tok_best = v; }
    }
  }
#pragma unroll
  for (int o = 1; o <= 2; o <<= 1) {
    float y2 = __shfl_xor_sync(0xffffffffu, y_best, o);
    int t2 = __shfl_xor_sync(0xffffffffu, tok_best, o);
    if (y2 > y_best || (y2 == y_best && t2 < tok_best)) { y_best = y2; tok_best = t2; }
  }
  bool active_next = false;
  if (g == 0 && valid) {
    const int tok = tok_best;
    float logits[VTOT];
#pragma unroll
    for (int v = 0; v < VTOT; v++) logits[v] = p[v] + bs[v];
    float mx = logits[0];
#pragma unroll
    for (int v = 1; v < VTOT; v++) mx = fmaxf(mx, logits[v]);
    float ssum = 0.f;
#pragma unroll
    for (int v = 0; v < VTOT; v++)
      ssum = __fadd_rn(ssum, __nv_expf(__fadd_rn(logits[v], -mx)));
    float lp = (logits[tok] - mx) - __nv_logf(ssum);
    out[(size_t)row * 36 + t * VTOT + tok] = 1.f;
    out[(size_t)B_TOT * 36 + row] += lp;
    const bool is_stop = (tok == VTOT - 1);
    if (!is_stop) out[(size_t)B_TOT * 37 + row] += 1.f;
    g_state[row] = (unsigned char)(tok | (is_stop ? 8 : 0));
    active_next = !is_stop;
  }
  unsigned ballot = __ballot_sync(0xffffffffu, active_next);
  int warp_total = __popc(ballot);
  int rank = __popc(ballot & ((1u << lane) - 1u));
  if (lane == 0) wcnt[wid] = warp_total;
  __syncthreads();
  if (tid == 0) {
    int ssum = 0;
#pragma unroll
    for (int w = 0; w < 8; w++) { wpre[w] = ssum; ssum += wcnt[w]; }
    sbase = (ssum > 0) ? atomicAdd(&g_cnt[t + 1], ssum) : 0;
  }
  __syncthreads();
  if (active_next) permN[sbase + wpre[wid] + rank] = row;
}

// ---------------- launch -------------------------------------------------------
extern "C" void kernel_launch(void* const* d_in, const int* in_sizes, int n_in,
                              void* d_out, int out_size) {
  const float* x           = (const float*)d_in[0];
  const float* W_enc       = (const float*)d_in[1];
  const float* b_enc       = (const float*)d_in[2];
  const float* W_embed     = (const float*)d_in[3];
  const float* b_embed     = (const float*)d_in[4];
  const float* W_z         = (const float*)d_in[5];
  const float* b_z         = (const float*)d_in[6];
  const float* W_r         = (const float*)d_in[7];
  const float* b_r         = (const float*)d_in[8];
  const float* W_h         = (const float*)d_in[9];
  const float* b_h         = (const float*)d_in[10];
  const float* W_out       = (const float*)d_in[11];
  const float* b_out       = (const float*)d_in[12];
  const float* start_embed = (const float*)d_in[13];
  float* out = (float*)d_out;

  // zero message region asynchronously (graph-capturable)
  cudaMemsetAsync(out, 0, (size_t)B_TOT * 36 * sizeof(float));
  init_kernel<<<B_TOT / 256, 256>>>(out);
  dim3 gE(8, 3);
  precompute_E<<<gE, 256>>>(W_embed, b_embed, W_z, b_z, W_r, b_r, W_h, b_h,
                            start_embed);

  const int GEMM_GRID = B_TOT / 64;
  gemm_k<0><<<GEMM_GRID, 256>>>(x, D_IN, D_IN, W_enc, nullptr, b_enc, 0);

  const float* Wz_bot = W_z + HID * HID;
  const float* Wr_bot = W_r + HID * HID;
  const float* Wh_bot = W_h + HID * HID;

  for (int t = 0; t < TSTEPS; t++) {
    dim3 gZR(GEMM_GRID, 2);
    gemm_k<12><<<gZR, 256>>>(nullptr, HID, HID, Wz_bot, Wr_bot, nullptr, t);
    gemm_k<3><<<GEMM_GRID, 256>>>(nullptr, HID, HID, Wh_bot, nullptr, nullptr, t);
    sample_step<<<B_TOT / 64, 256>>>(W_out, b_out, out, t);
  }
}

// round 15
// speedup vs baseline: 1.0860x; 1.0860x over previous
#include <cuda_runtime.h>
#include <cstdint>
#include <cstddef>
#include <math.h>

#define B_TOT 131072
#define D_IN  128
#define HID   256
#define VTOT  6
#define TSTEPS 6

typedef unsigned long long ull;

extern "C" __device__ float __nv_logf(float);
extern "C" __device__ float __nv_expf(float);

// ---------------- persistent device scratch ---------------------------------
__device__ __align__(16) float g_h [(size_t)B_TOT * HID];
__device__ __align__(16) float g_z [(size_t)B_TOT * HID];
__device__ __align__(16) float g_rh[(size_t)B_TOT * HID];
__device__ unsigned char g_state[B_TOT];
__device__ __align__(16) float g_E[3][8][HID];
__device__ uint32_t g_keyw[12];
__device__ int g_perm[2][B_TOT];
__device__ int g_cnt[TSTEPS + 2];

// ---------------- threefry2x32 (exact JAX schedule) -------------------------
__device__ __forceinline__ void threefry2x32(uint32_t k0, uint32_t k1,
                                             uint32_t c0, uint32_t c1,
                                             uint32_t& o0, uint32_t& o1) {
  uint32_t ks2 = k0 ^ k1 ^ 0x1BD11BDAu;
  uint32_t x0 = c0 + k0, x1 = c1 + k1;
#define TF_R(r) { x0 += x1; x1 = (x1 << (r)) | (x1 >> (32 - (r))); x1 ^= x0; }
  TF_R(13) TF_R(15) TF_R(26) TF_R(6)
  x0 += k1;  x1 += ks2 + 1u;
  TF_R(17) TF_R(29) TF_R(16) TF_R(24)
  x0 += ks2; x1 += k0 + 2u;
  TF_R(13) TF_R(15) TF_R(26) TF_R(6)
  x0 += k0;  x1 += k1 + 3u;
  TF_R(17) TF_R(29) TF_R(16) TF_R(24)
  x0 += k1;  x1 += ks2 + 4u;
  TF_R(13) TF_R(15) TF_R(26) TF_R(6)
  x0 += ks2; x1 += k0 + 5u;
#undef TF_R
  o0 = x0; o1 = x1;
}

// ---------------- helpers -----------------------------------------------------
__device__ __forceinline__ void fma2(ull& d, ull a, ull b) {
  asm("fma.rn.f32x2 %0, %1, %2, %0;" : "+l"(d) : "l"(a), "l"(b));
}
__device__ __forceinline__ ull pack2(float a) {
  ull r; asm("mov.b64 %0, {%1, %1};" : "=l"(r) : "f"(a)); return r;
}
__device__ __forceinline__ float2 unpack2(ull v) {
  float2 r; asm("mov.b64 {%0, %1}, %2;" : "=f"(r.x), "=f"(r.y) : "l"(v)); return r;
}
__device__ __forceinline__ void cp16(void* dst, const void* src) {
  unsigned d = (unsigned)__cvta_generic_to_shared(dst);
  asm volatile("cp.async.cg.shared.global [%0], [%1], 16;" :: "r"(d), "l"(src));
}
__device__ __forceinline__ float xla_tanh(float x) {
  float ax = fabsf(x);
  if (ax < 0.0004f) return x;
  float xc = fminf(fmaxf(x, -9.0f), 9.0f);
  float x2 = __fmul_rn(xc, xc);
  float num = -2.76076847742355e-16f;
  num = __fadd_rn(__fmul_rn(x2, num), 2.00018790482477e-13f);
  num = __fadd_rn(__fmul_rn(x2, num), -8.60467152213735e-11f);
  num = __fadd_rn(__fmul_rn(x2, num), 5.12229709037114e-08f);
  num = __fadd_rn(__fmul_rn(x2, num), 1.48572235717979e-05f);
  num = __fadd_rn(__fmul_rn(x2, num), 6.37261928875436e-04f);
  num = __fadd_rn(__fmul_rn(x2, num), 4.89352455891786e-03f);
  num = __fmul_rn(xc, num);
  float den = 1.19825839466702e-06f;
  den = __fadd_rn(__fmul_rn(x2, den), 1.18534705686654e-04f);
  den = __fadd_rn(__fmul_rn(x2, den), 2.26843463243900e-03f);
  den = __fadd_rn(__fmul_rn(x2, den), 4.89352518554385e-03f);
  return __fdiv_rn(num, den);
}
__device__ __forceinline__ float sigmoid_(float x) {
  return __fadd_rn(0.5f, __fmul_rn(0.5f, xla_tanh(__fmul_rn(0.5f, x))));
}

// ---------------- init --------------------------------------------------------
__global__ void init_kernel(float* __restrict__ out) {
  const int gid = blockIdx.x * blockDim.x + threadIdx.x;
  if (gid < B_TOT) {
    out[(size_t)B_TOT * 36 + gid] = 0.f;
    out[(size_t)B_TOT * 37 + gid] = 0.f;
    g_state[gid] = 7;
    g_perm[0][gid] = gid;
  }
  if (gid < TSTEPS + 2) g_cnt[gid] = (gid == 0) ? B_TOT : 0;
  if (gid < 6) {
    uint32_t a, b;
    threefry2x32(0u, 42u, 0u, (uint32_t)gid, a, b);
    g_keyw[2 * gid]     = a;
    g_keyw[2 * gid + 1] = b;
  }
}

// ---------------- precompute E tables ----------------------------------------
__global__ void precompute_E(const float* __restrict__ W_embed,
                             const float* __restrict__ b_embed,
                             const float* __restrict__ Wz, const float* __restrict__ bz,
                             const float* __restrict__ Wr, const float* __restrict__ br,
                             const float* __restrict__ Wh, const float* __restrict__ bh,
                             const float* __restrict__ start_embed) {
  int s = blockIdx.x, m = blockIdx.y, j = threadIdx.x;
  const float* W  = (m == 0) ? Wz : (m == 1) ? Wr : Wh;
  const float* bb = (m == 0) ? bz : (m == 1) ? br : bh;
  float acc = bb[j];
  for (int k = 0; k < HID; k++) {
    float e;
    if (s == 7) e = start_embed[k];
    else { e = b_embed[k]; if (s < 6) e += W_embed[s * HID + k]; }
    acc = fmaf(e, W[k * HID + j], acc);
  }
  g_E[m][s][j] = acc;
}

// ---------------- GEMM (exact R8 proven config: BM64/BN256/BK16) -------------
template <int MODE>
__global__ void __launch_bounds__(256, 2) gemm_k(
    const float* __restrict__ Aext, int lda, int K,
    const float* __restrict__ Bw, const float* __restrict__ bias, int t) {
  constexpr int BM = 64, BN = 256, BK = 16, APAD = BM + 4;
  __shared__ __align__(16) float As[2][BK][APAD];
  __shared__ __align__(16) float Bs[2][BK][BN];
  __shared__ int sPerm[BM];

  const int rowBase = blockIdx.x * BM;
  int cnt = B_TOT;
  if (MODE != 0) {
    cnt = g_cnt[t];
    if (rowBase >= cnt) return;
    const int* perm = g_perm[t & 1];
    if (threadIdx.x < BM) {
      int j = rowBase + threadIdx.x;
      sPerm[threadIdx.x] = perm[j < cnt ? j : rowBase];
    }
    __syncthreads();
  }

  const float* A = (MODE == 0) ? Aext : (MODE == 3 ? g_rh : g_h);
  const int tid = threadIdx.x;
  const int tc = tid & 31;
  const int tr = tid >> 5;

  const int a_row = tid >> 2;
  const int a_seg = (tid & 3) << 2;
  const int arow_g = (MODE == 0) ? (rowBase + a_row) : sPerm[a_row];
  const float* Ag = A + (size_t)arow_g * lda + a_seg;

  ull acc[8][4];
#pragma unroll
  for (int r = 0; r < 8; r++)
#pragma unroll
    for (int p = 0; p < 4; p++) acc[r][p] = 0ull;

  const int NC = K / BK;

  float4 rA = *reinterpret_cast<const float4*>(Ag);
#pragma unroll
  for (int i = 0; i < 4; i++) {
    int idx = tid + i * 256, kr = idx >> 6, cs = (idx & 63) << 2;
    cp16(&Bs[0][kr][cs], Bw + (size_t)kr * BN + cs);
  }
  asm volatile("cp.async.commit_group;");
  As[0][a_seg + 0][a_row] = rA.x;
  As[0][a_seg + 1][a_row] = rA.y;
  As[0][a_seg + 2][a_row] = rA.z;
  As[0][a_seg + 3][a_row] = rA.w;
  if (NC > 1) rA = *reinterpret_cast<const float4*>(Ag + BK);

  for (int c = 0; c < NC; c++) {
    asm volatile("cp.async.wait_group 0;");
    __syncthreads();
    if (c + 1 < NC) {
      const int nbuf = (c + 1) & 1;
#pragma unroll
      for (int i = 0; i < 4; i++) {
        int idx = tid + i * 256, kr = idx >> 6, cs = (idx & 63) << 2;
        cp16(&Bs[nbuf][kr][cs], Bw + (size_t)((c + 1) * BK + kr) * BN + cs);
      }
      asm volatile("cp.async.commit_group;");
      As[nbuf][a_seg + 0][a_row] = rA.x;
      As[nbuf][a_seg + 1][a_row] = rA.y;
      As[nbuf][a_seg + 2][a_row] = rA.z;
      As[nbuf][a_seg + 3][a_row] = rA.w;
      if (c + 2 < NC) rA = *reinterpret_cast<const float4*>(Ag + (c + 2) * BK);
    }
    const int buf = c & 1;
#pragma unroll
    for (int k = 0; k < BK; k++) {
      ulonglong2 b01 = *reinterpret_cast<const ulonglong2*>(&Bs[buf][k][tc * 4]);
      ulonglong2 b23 = *reinterpret_cast<const ulonglong2*>(&Bs[buf][k][128 + tc * 4]);
      float4 a0 = *reinterpret_cast<const float4*>(&As[buf][k][tr * 8]);
      float4 a1 = *reinterpret_cast<const float4*>(&As[buf][k][tr * 8 + 4]);
      ull ap[8];
      ap[0] = pack2(a0.x); ap[1] = pack2(a0.y); ap[2] = pack2(a0.z); ap[3] = pack2(a0.w);
      ap[4] = pack2(a1.x); ap[5] = pack2(a1.y); ap[6] = pack2(a1.z); ap[7] = pack2(a1.w);
#pragma unroll
      for (int r = 0; r < 8; r++) {
        fma2(acc[r][0], ap[r], b01.x);
        fma2(acc[r][1], ap[r], b01.y);
        fma2(acc[r][2], ap[r], b23.x);
        fma2(acc[r][3], ap[r], b23.y);
      }
    }
  }

  const int c0 = tc * 4;
#pragma unroll
  for (int r = 0; r < 8; r++) {
    const int iRow = rowBase + tr * 8 + r;
    if (MODE != 0 && iRow >= cnt) continue;
    const int rr = (MODE == 0) ? iRow : sPerm[tr * 8 + r];
    float f[8];
    {
      float2 v;
      v = unpack2(acc[r][0]); f[0] = v.x; f[1] = v.y;
      v = unpack2(acc[r][1]); f[2] = v.x; f[3] = v.y;
      v = unpack2(acc[r][2]); f[4] = v.x; f[5] = v.y;
      v = unpack2(acc[r][3]); f[6] = v.x; f[7] = v.y;
    }
    const size_t base0 = (size_t)rr * HID + c0;
    const size_t base1 = base0 + 128;
    if (MODE == 0) {
      float4 b0 = *reinterpret_cast<const float4*>(&bias[c0]);
      float4 b1 = *reinterpret_cast<const float4*>(&bias[128 + c0]);
      *reinterpret_cast<float4*>(&g_h[base0]) =
          make_float4(f[0] + b0.x, f[1] + b0.y, f[2] + b0.z, f[3] + b0.w);
      *reinterpret_cast<float4*>(&g_h[base1]) =
          make_float4(f[4] + b1.x, f[5] + b1.y, f[6] + b1.z, f[7] + b1.w);
    } else {
      const int s = g_state[rr] & 7;
      const float* Em = g_E[MODE - 1][s];
      float4 e0 = *reinterpret_cast<const float4*>(&Em[c0]);
      float4 e1 = *reinterpret_cast<const float4*>(&Em[128 + c0]);
      float pre[8] = {f[0] + e0.x, f[1] + e0.y, f[2] + e0.z, f[3] + e0.w,
                      f[4] + e1.x, f[5] + e1.y, f[6] + e1.z, f[7] + e1.w};
      if (MODE == 1) {
        *reinterpret_cast<float4*>(&g_z[base0]) =
            make_float4(sigmoid_(pre[0]), sigmoid_(pre[1]),
                        sigmoid_(pre[2]), sigmoid_(pre[3]));
        *reinterpret_cast<float4*>(&g_z[base1]) =
            make_float4(sigmoid_(pre[4]), sigmoid_(pre[5]),
                        sigmoid_(pre[6]), sigmoid_(pre[7]));
      } else if (MODE == 2) {
        float4 h0 = *reinterpret_cast<const float4*>(&g_h[base0]);
        float4 h1 = *reinterpret_cast<const float4*>(&g_h[base1]);
        *reinterpret_cast<float4*>(&g_rh[base0]) =
            make_float4(sigmoid_(pre[0]) * h0.x, sigmoid_(pre[1]) * h0.y,
                        sigmoid_(pre[2]) * h0.z, sigmoid_(pre[3]) * h0.w);
        *reinterpret_cast<float4*>(&g_rh[base1]) =
            make_float4(sigmoid_(pre[4]) * h1.x, sigmoid_(pre[5]) * h1.y,
                        sigmoid_(pre[6]) * h1.z, sigmoid_(pre[7]) * h1.w);
      } else {
        float4 z0 = *reinterpret_cast<const float4*>(&g_z[base0]);
        float4 z1 = *reinterpret_cast<const float4*>(&g_z[base1]);
        float4 h0 = *reinterpret_cast<const float4*>(&g_h[base0]);
        float4 h1 = *reinterpret_cast<const float4*>(&g_h[base1]);
        float4 o0, o1;
        o0.x = (1.f - z0.x) * h0.x + z0.x * xla_tanh(pre[0]);
        o0.y = (1.f - z0.y) * h0.y + z0.y * xla_tanh(pre[1]);
        o0.z = (1.f - z0.z) * h0.z + z0.z * xla_tanh(pre[2]);
        o0.w = (1.f - z0.w) * h0.w + z0.w * xla_tanh(pre[3]);
        o1.x = (1.f - z1.x) * h1.x + z1.x * xla_tanh(pre[4]);
        o1.y = (1.f - z1.y) * h1.y + z1.y * xla_tanh(pre[5]);
        o1.z = (1.f - z1.z) * h1.z + z1.z * xla_tanh(pre[6]);
        o1.w = (1.f - z1.w) * h1.w + z1.w * xla_tanh(pre[7]);
        *reinterpret_cast<float4*>(&g_h[base0]) = o0;
        *reinterpret_cast<float4*>(&g_h[base1]) = o1;
      }
    }
  }
}

// ---------------- sampler v3: 8 lanes/row (coalesced), warp = 4 rows ----------
__global__ void __launch_bounds__(256) sample_step(
    const float* __restrict__ W_out, const float* __restrict__ b_out,
    float* __restrict__ out, int t) {
  __shared__ float Ws[HID * VTOT];
  __shared__ float bs[8];
  __shared__ int wcnt[8], wpre[8], sbase;
  const int cnt = g_cnt[t];
  const int base_i = blockIdx.x * 32;     // 32 rows per CTA
  if (base_i >= cnt) return;
  const bool last = (t == TSTEPS - 1);
  const int* perm = g_perm[t & 1];
  int* permN = g_perm[(t + 1) & 1];
  const int tid = threadIdx.x;
  for (int i = tid; i < HID * VTOT; i += 256) Ws[i] = W_out[i];
  if (tid < VTOT) bs[tid] = b_out[tid];
  __syncthreads();

  const int wid = tid >> 5, lane = tid & 31;
  const int j = lane & 7;                 // col-eighth within row
  const int rloc = lane >> 3;             // row within warp (0..3)
  const int i = base_i + wid * 4 + rloc;
  const bool valid = (i < cnt);
  const int row = perm[valid ? i : base_i];
  const float* h = g_h + (size_t)row * HID;

  // partials over cols {j*4 + q*32}, q=0..7: each warp-load = 4 rows x 128B
  float p[VTOT];
#pragma unroll
  for (int v = 0; v < VTOT; v++) p[v] = 0.f;
#pragma unroll
  for (int q = 0; q < 8; q++) {
    const int c = q * 32 + j * 4;
    float4 hv = *reinterpret_cast<const float4*>(h + c);
    const float* w = &Ws[c * VTOT];
#pragma unroll
    for (int v = 0; v < VTOT; v++) {
      p[v] = fmaf(hv.x, w[v], p[v]);
      p[v] = fmaf(hv.y, w[VTOT + v], p[v]);
      p[v] = fmaf(hv.z, w[2 * VTOT + v], p[v]);
      p[v] = fmaf(hv.w, w[3 * VTOT + v], p[v]);
    }
  }
  // butterfly over the 8-lane group
#pragma unroll
  for (int o = 1; o <= 4; o <<= 1)
#pragma unroll
    for (int v = 0; v < VTOT; v++) p[v] += __shfl_xor_sync(0xffffffffu, p[v], o);

  // gumbel: lanes j<6 each handle v=j (exact partitionable threefry)
  const uint32_t k0 = g_keyw[2 * t], k1 = g_keyw[2 * t + 1];
  float y_best = __int_as_float(0xff800000);
  int tok_best = 127;
  if (j < VTOT) {
    uint32_t idx = (uint32_t)row * VTOT + j;
    uint32_t o0, o1;
    threefry2x32(k0, k1, 0u, idx, o0, o1);
    uint32_t bits = o0 ^ o1;
    uint32_t fb = (bits >> 9) | 0x3f800000u;
    float fu = __fadd_rn(__uint_as_float(fb), -1.0f);
    float u = fmaxf(1.17549435e-38f, fu);
    float gf = -__nv_logf(-__nv_logf(u));
    y_best = (p[j] + bs[j]) + gf;
    tok_best = j;
  }
#pragma unroll
  for (int o = 1; o <= 4; o <<= 1) {
    float y2 = __shfl_xor_sync(0xffffffffu, y_best, o);
    int t2 = __shfl_xor_sync(0xffffffffu, tok_best, o);
    if (y2 > y_best || (y2 == y_best && t2 < tok_best)) { y_best = y2; tok_best = t2; }
  }

  bool active_next = false;
  if (j == 0 && valid) {
    const int tok = tok_best;
    float logits[VTOT];
#pragma unroll
    for (int v = 0; v < VTOT; v++) logits[v] = p[v] + bs[v];
    float mx = logits[0];
#pragma unroll
    for (int v = 1; v < VTOT; v++) mx = fmaxf(mx, logits[v]);
    float ssum = 0.f;
#pragma unroll
    for (int v = 0; v < VTOT; v++)
      ssum = __fadd_rn(ssum, __nv_expf(__fadd_rn(logits[v], -mx)));
    float lp = (logits[tok] - mx) - __nv_logf(ssum);
    out[(size_t)row * 36 + t * VTOT + tok] = 1.f;
    out[(size_t)B_TOT * 36 + row] += lp;
    const bool is_stop = (tok == VTOT - 1);
    if (!is_stop) out[(size_t)B_TOT * 37 + row] += 1.f;
    if (!last) {
      g_state[row] = (unsigned char)(tok | (is_stop ? 8 : 0));
      active_next = !is_stop;
    }
  }
  if (last) return;

  // compaction: survivors -> permN (<=4 set bits per warp)
  unsigned ballot = __ballot_sync(0xffffffffu, active_next);
  int warp_total = __popc(ballot);
  int rank = __popc(ballot & ((1u << lane) - 1u));
  if (lane == 0) wcnt[wid] = warp_total;
  __syncthreads();
  if (tid == 0) {
    int ssum = 0;
#pragma unroll
    for (int w = 0; w < 8; w++) { wpre[w] = ssum; ssum += wcnt[w]; }
    sbase = (ssum > 0) ? atomicAdd(&g_cnt[t + 1], ssum) : 0;
  }
  __syncthreads();
  if (active_next) permN[sbase + wpre[wid] + rank] = row;
}

// ---------------- launch -------------------------------------------------------
extern "C" void kernel_launch(void* const* d_in, const int* in_sizes, int n_in,
                              void* d_out, int out_size) {
  const float* x           = (const float*)d_in[0];
  const float* W_enc       = (const float*)d_in[1];
  const float* b_enc       = (const float*)d_in[2];
  const float* W_embed     = (const float*)d_in[3];
  const float* b_embed     = (const float*)d_in[4];
  const float* W_z         = (const float*)d_in[5];
  const float* b_z         = (const float*)d_in[6];
  const float* W_r         = (const float*)d_in[7];
  const float* b_r         = (const float*)d_in[8];
  const float* W_h         = (const float*)d_in[9];
  const float* b_h         = (const float*)d_in[10];
  const float* W_out       = (const float*)d_in[11];
  const float* b_out       = (const float*)d_in[12];
  const float* start_embed = (const float*)d_in[13];
  float* out = (float*)d_out;

  cudaMemsetAsync(out, 0, (size_t)B_TOT * 36 * sizeof(float));
  init_kernel<<<B_TOT / 256, 256>>>(out);
  dim3 gE(8, 3);
  precompute_E<<<gE, 256>>>(W_embed, b_embed, W_z, b_z, W_r, b_r, W_h, b_h,
                            start_embed);

  const int GEMM_GRID = B_TOT / 64;
  gemm_k<0><<<GEMM_GRID, 256>>>(x, D_IN, D_IN, W_enc, b_enc, 0);

  const float* Wz_bot = W_z + HID * HID;
  const float* Wr_bot = W_r + HID * HID;
  const float* Wh_bot = W_h + HID * HID;

  for (int t = 0; t < TSTEPS; t++) {
    gemm_k<1><<<GEMM_GRID, 256>>>(nullptr, HID, HID, Wz_bot, nullptr, t);
    gemm_k<2><<<GEMM_GRID, 256>>>(nullptr, HID, HID, Wr_bot, nullptr, t);
    gemm_k<3><<<GEMM_GRID, 256>>>(nullptr, HID, HID, Wh_bot, nullptr, t);
    sample_step<<<B_TOT / 32, 256>>>(W_out, b_out, out, t);
  }
}